// round 4
// baseline (speedup 1.0000x reference)
#include <cuda_runtime.h>
#include <cuda_bf16.h>
#include <stdint.h>

// Problem constants
#define PD 64      // splits
#define KD 64      // samples per side
#define ND 128     // points per split
#define DD 2048    // feature dim
#define NCH 2      // D halves -> 128 CTAs for the gram stage
#define KC (DD / NCH)     // 1024 K per CTA
#define NCHK (KC / 64)    // 16 chunks of 64 K

// Scratch (device globals; no allocation allowed)
__device__ float g_part[NCH][PD][ND][ND];  // partial grams, 8 MB (L2-resident)
__device__ float g_sums[PD][4];            // xx, xy, yx, yy per split
__device__ float g_l2max[PD];

__device__ __forceinline__ uint32_t smem_u32(const void* p) {
    uint32_t a;
    asm("{ .reg .u64 t; cvta.to.shared.u64 t, %1; cvt.u32.u64 %0, t; }"
        : "=r"(a) : "l"(p));
    return a;
}

__device__ __forceinline__ void ldsm_x4(uint32_t& r0, uint32_t& r1, uint32_t& r2,
                                        uint32_t& r3, uint32_t addr) {
    asm volatile("ldmatrix.sync.aligned.m8n8.x4.shared.b16 {%0,%1,%2,%3}, [%4];"
                 : "=r"(r0), "=r"(r1), "=r"(r2), "=r"(r3) : "r"(addr));
}

__device__ __forceinline__ void mma_bf16(float* c, const uint32_t* a, const uint32_t* b) {
    asm volatile(
        "mma.sync.aligned.m16n8k16.row.col.f32.bf16.bf16.f32 "
        "{%0,%1,%2,%3}, {%4,%5,%6,%7}, {%8,%9}, {%0,%1,%2,%3};"
        : "+f"(c[0]), "+f"(c[1]), "+f"(c[2]), "+f"(c[3])
        : "r"(a[0]), "r"(a[1]), "r"(a[2]), "r"(a[3]), "r"(b[0]), "r"(b[1]));
}

// ---------------------------------------------------------------------------
// Kernel 1: partial Gram via HMMA. blockIdx.x = D-half, blockIdx.y = split.
// 256 threads = 8 warps; warp tile 32x64 of the 128x128 output.
// SMEM: double-buffered 128 x 64 bf16 tiles (rows padded to 72).
// Register prefetch depth 2: LDG for chunk c+2 issues at iteration c.
// ---------------------------------------------------------------------------
__global__ void __launch_bounds__(256) gram_kernel(const float* __restrict__ src,
                                                   const float* __restrict__ tgt) {
    const int nc = blockIdx.x;
    const int p  = blockIdx.y;
    const int t  = threadIdx.x;
    const int lane = t & 31;
    const int w    = t >> 5;

    __shared__ __align__(16) __nv_bfloat16 tile[2][ND][72];

    // ---- loader mapping: thread t loads 8 rows (rb + 16s), one float4 each ----
    const int f4 = t & 15;          // float4 column 0..15 (covers 64 floats)
    const int rb = t >> 4;          // base row 0..15
    const float* rowp[8];
#pragma unroll
    for (int s = 0; s < 8; s++) {
        int r = rb + 16 * s;
        const float* base = (r < KD) ? (src + (size_t)(p * KD + r) * DD)
                                     : (tgt + (size_t)(p * KD + (r - KD)) * DD);
        rowp[s] = base + nc * KC + f4 * 4;
    }
    char* tbase[2] = { (char*)&tile[0][0][0], (char*)&tile[1][0][0] };
    uint32_t sts[8];
#pragma unroll
    for (int s = 0; s < 8; s++)
        sts[s] = (uint32_t)((rb + 16 * s) * 144 + f4 * 8);

    // ---- mma mapping: warp tile at (wm, wn) ----
    const int wm = (w & 3) << 5;    // 0,32,64,96
    const int wn = (w >> 2) << 6;   // 0,64
    uint32_t tb[2] = { smem_u32(tbase[0]), smem_u32(tbase[1]) };
    uint32_t aaddr[2][2], baddr[2][4];
#pragma unroll
    for (int b = 0; b < 2; b++) {
#pragma unroll
        for (int mi = 0; mi < 2; mi++)
            aaddr[b][mi] = tb[b] + (uint32_t)((wm + mi * 16 + (lane & 15)) * 144
                                              + (lane >> 4) * 16);
#pragma unroll
        for (int nj = 0; nj < 4; nj++)
            baddr[b][nj] = tb[b] + (uint32_t)((wn + nj * 16 + ((lane >> 4) << 3)
                                               + (lane & 7)) * 144
                                              + ((lane >> 3) & 1) * 16);
    }

    float acc[2][8][4];
#pragma unroll
    for (int mi = 0; mi < 2; mi++)
#pragma unroll
        for (int nj = 0; nj < 8; nj++)
#pragma unroll
            for (int r = 0; r < 4; r++) acc[mi][nj][r] = 0.f;

    // ---- prologue: LDG chunks 0,1 into registers; STS chunk 0 ----
    float4 v[2][8];
#pragma unroll
    for (int s = 0; s < 8; s++) v[0][s] = *(const float4*)(rowp[s]);
#pragma unroll
    for (int s = 0; s < 8; s++) v[1][s] = *(const float4*)(rowp[s] + 64);
#pragma unroll
    for (int s = 0; s < 8; s++) {
        __nv_bfloat162 lo = __floats2bfloat162_rn(v[0][s].x, v[0][s].y);
        __nv_bfloat162 hi = __floats2bfloat162_rn(v[0][s].z, v[0][s].w);
        uint2 u = { *(uint32_t*)&lo, *(uint32_t*)&hi };
        *(uint2*)(tbase[0] + sts[s]) = u;
    }

    for (int ch = 0; ch < NCHK; ch++) {
        const int b = ch & 1;
        // STS chunk ch+1 into tile[b^1] (its last readers synced at iter ch-1)
        if (ch + 1 < NCHK) {
            char* dst = tbase[b ^ 1];
#pragma unroll
            for (int s = 0; s < 8; s++) {
                __nv_bfloat162 lo = __floats2bfloat162_rn(v[(ch + 1) & 1][s].x,
                                                          v[(ch + 1) & 1][s].y);
                __nv_bfloat162 hi = __floats2bfloat162_rn(v[(ch + 1) & 1][s].z,
                                                          v[(ch + 1) & 1][s].w);
                uint2 u = { *(uint32_t*)&lo, *(uint32_t*)&hi };
                *(uint2*)(dst + sts[s]) = u;
            }
        }
        // LDG chunk ch+2 into v[b] (chunk ch already consumed by STS at iter ch-1)
        if (ch + 2 < NCHK) {
#pragma unroll
            for (int s = 0; s < 8; s++)
                v[b][s] = *(const float4*)(rowp[s] + (ch + 2) * 64);
        }
        __syncthreads();   // STS of chunks ch (prologue/prev) .. ch+1 visible

        // MMA on tile[b] (chunk ch)
#pragma unroll
        for (int k16 = 0; k16 < 4; k16++) {
            uint32_t a[2][4], bb[8][2];
            ldsm_x4(a[0][0], a[0][1], a[0][2], a[0][3], aaddr[b][0] + k16 * 32);
            ldsm_x4(a[1][0], a[1][1], a[1][2], a[1][3], aaddr[b][1] + k16 * 32);
#pragma unroll
            for (int nj = 0; nj < 4; nj++)
                ldsm_x4(bb[2 * nj][0], bb[2 * nj][1], bb[2 * nj + 1][0],
                        bb[2 * nj + 1][1], baddr[b][nj] + k16 * 32);
#pragma unroll
            for (int mi = 0; mi < 2; mi++)
#pragma unroll
                for (int nj = 0; nj < 8; nj++)
                    mma_bf16(acc[mi][nj], a[mi], bb[nj]);
        }
        __syncthreads();   // MMA reads of tile[b] done before iter ch+1 STS overwrites it
    }

    // write accumulators: lane l owns rows (l>>2, l>>2+8), cols (l&3)*2 (+1)
    float* outp = &g_part[nc][p][0][0];
    const int rr = lane >> 2;
    const int cc = (lane & 3) * 2;
#pragma unroll
    for (int mi = 0; mi < 2; mi++)
#pragma unroll
        for (int nj = 0; nj < 8; nj++) {
            int row = wm + mi * 16 + rr;
            int col = wn + nj * 8 + cc;
            *(float2*)&outp[row * ND + col] =
                make_float2(acc[mi][nj][0], acc[mi][nj][1]);
            *(float2*)&outp[(row + 8) * ND + col] =
                make_float2(acc[mi][nj][2], acc[mi][nj][3]);
        }
}

// ---------------------------------------------------------------------------
// Kernel 2: per-split MMD epilogue. One CTA per split, 256 threads.
// Thread layout: quadrant q = t>>6 (bit1 = i-half, bit0 = j-half),
// u = t&63 -> row i = (q>>1)*64 + u, cols jb = (q&1)*64 .. +63.
// l2 row-half kept in registers across both passes.
// Exp trick: sum_m exp(-l2*inv[m]) = z + z^2 + z^4 + z^8 + z^16,
// z = exp(-l2*inv4) (the +1e-9 perturbation is ~1e-12 relative; negligible).
// ---------------------------------------------------------------------------
__global__ void __launch_bounds__(256) mmd_kernel() {
    const int p = blockIdx.x;
    const int t = threadIdx.x;
    const int q = t >> 6;
    const int u = t & 63;
    const int i = ((q >> 1) << 6) + u;
    const int jb = (q & 1) << 6;

    __shared__ float diag[ND];
    __shared__ float red[256], red2[256];
    __shared__ float s_bw;

    const float* p0 = &g_part[0][p][0][0];
    const float* p1 = &g_part[1][p][0][0];

    float g[64];
#pragma unroll
    for (int j4 = 0; j4 < 16; j4++) {
        float4 A = *(const float4*)&p0[i * ND + jb + j4 * 4];
        float4 B = *(const float4*)&p1[i * ND + jb + j4 * 4];
        g[4 * j4 + 0] = A.x + B.x;
        g[4 * j4 + 1] = A.y + B.y;
        g[4 * j4 + 2] = A.z + B.z;
        g[4 * j4 + 3] = A.w + B.w;
    }
    if (t < ND) diag[t] = p0[t * ND + t] + p1[t * ND + t];
    __syncthreads();

    const float di = diag[i];

    // Pass 1: l2 (stored in-place into g), sum(l2), max(l2)
    float lsum = 0.f, lmax = 0.f;
#pragma unroll
    for (int jj = 0; jj < 64; jj++) {
        float l2 = di + diag[jb + jj] - 2.f * g[jj];
        g[jj] = l2;
        lsum += l2;
        lmax = fmaxf(lmax, l2);
    }
    red[t] = lsum;
    red2[t] = lmax;
    __syncthreads();
#pragma unroll
    for (int s = 128; s > 0; s >>= 1) {
        if (t < s) {
            red[t] += red[t + s];
            red2[t] = fmaxf(red2[t], red2[t + s]);
        }
        __syncthreads();
    }
    if (t == 0) {
        s_bw = red[0] / (float)(ND * ND - ND) * 0.25f;  // /(n^2-n)/2^(5/2 floor)
        g_l2max[p] = red2[0];
    }
    __syncthreads();

    const float inv4 = 1.f / (s_bw * 16.f + 1e-9f);

    // Pass 2: 5-RBF kernel sum via repeated squaring (1 expf per element)
    float qs = 0.f;
#pragma unroll
    for (int jj = 0; jj < 64; jj++) {
        float z = __expf(-g[jj] * inv4);
        float z2 = z * z;
        float z4 = z2 * z2;
        float z8 = z4 * z4;
        float z16 = z8 * z8;
        qs += z + z2 + z4 + z8 + z16;
    }
    red[t] = qs;
    __syncthreads();
#pragma unroll
    for (int s = 32; s > 0; s >>= 1) {
        if (u < s) red[t] += red[t + s];
        __syncthreads();
    }
    if (u == 0) g_sums[p][q] = red[t];   // q: 0=xx, 1=xy, 2=yx, 3=yy
}

// ---------------------------------------------------------------------------
// Kernel 3: fixed-order final reduction across splits -> 6 output scalars.
// ---------------------------------------------------------------------------
__global__ void finalize_kernel(float* __restrict__ out) {
    float X = 0.f, Y = 0.f, XY = 0.f, YX = 0.f;
    for (int p = 0; p < PD; p++) {
        X  += g_sums[p][0] * (1.f / 4096.f);
        XY += g_sums[p][1] * (1.f / 4096.f);
        YX += g_sums[p][2] * (1.f / 4096.f);
        Y  += g_sums[p][3] * (1.f / 4096.f);
    }
    out[0] = (X + Y - XY - YX) * (1.f / 64.f);  // total_loss
    out[1] = g_l2max[PD - 1];                   // max(l2[-1])
    out[2] = X * (1.f / 64.f);                  // sum(xx)/P
    out[3] = Y * (1.f / 64.f);                  // sum(yy)/P
    out[4] = XY * (1.f / 64.f);                 // sum(xy)/P
    out[5] = YX * (1.f / 64.f);                 // sum(yx)/P
}

extern "C" void kernel_launch(void* const* d_in, const int* in_sizes, int n_in,
                              void* d_out, int out_size) {
    const float* src = (const float*)d_in[0];
    const float* tgt = (const float*)d_in[1];

    dim3 g1(NCH, PD);
    gram_kernel<<<g1, 256>>>(src, tgt);
    mmd_kernel<<<PD, 256>>>();
    finalize_kernel<<<1, 1>>>((float*)d_out);
}

// round 5
// speedup vs baseline: 1.5518x; 1.5518x over previous
#include <cuda_runtime.h>
#include <cuda_bf16.h>
#include <stdint.h>

// Problem constants
#define PD 64      // splits
#define KD 64      // samples per side
#define ND 128     // points per split
#define DD 2048    // feature dim
#define NCH 2      // D halves -> 128 CTAs for the gram stage
#define KC (DD / NCH)     // 1024 K per CTA
#define NCHK (KC / 64)    // 16 chunks of 64 K

// Scratch (device globals; no allocation allowed)
__device__ float g_part[NCH][PD][ND][ND];  // partial grams, 8 MB (L2-resident)
__device__ float g_sums[PD][4];            // xx, xy, yx, yy per split
__device__ float g_l2max[PD];
__device__ unsigned int g_ctr;             // zero-initialized; self-resetting

__device__ __forceinline__ uint32_t smem_u32(const void* p) {
    uint32_t a;
    asm("{ .reg .u64 t; cvta.to.shared.u64 t, %1; cvt.u32.u64 %0, t; }"
        : "=r"(a) : "l"(p));
    return a;
}

__device__ __forceinline__ void ldsm_x4(uint32_t& r0, uint32_t& r1, uint32_t& r2,
                                        uint32_t& r3, uint32_t addr) {
    asm volatile("ldmatrix.sync.aligned.m8n8.x4.shared.b16 {%0,%1,%2,%3}, [%4];"
                 : "=r"(r0), "=r"(r1), "=r"(r2), "=r"(r3) : "r"(addr));
}

__device__ __forceinline__ void mma_bf16(float* c, const uint32_t* a, const uint32_t* b) {
    asm volatile(
        "mma.sync.aligned.m16n8k16.row.col.f32.bf16.bf16.f32 "
        "{%0,%1,%2,%3}, {%4,%5,%6,%7}, {%8,%9}, {%0,%1,%2,%3};"
        : "+f"(c[0]), "+f"(c[1]), "+f"(c[2]), "+f"(c[3])
        : "r"(a[0]), "r"(a[1]), "r"(a[2]), "r"(a[3]), "r"(b[0]), "r"(b[1]));
}

// ---------------------------------------------------------------------------
// Kernel 1: partial Gram via HMMA. blockIdx.x = D-half, blockIdx.y = split.
// 256 threads = 8 warps; warp tile 32x64 of the 128x128 output.
// Loop order (proven in R3): LDG next -> MMA cur -> STS next -> one sync.
// New: LDSM fragments double-buffered across k16 steps so HMMA overlaps LDSM.
// ---------------------------------------------------------------------------
__global__ void __launch_bounds__(256) gram_kernel(const float* __restrict__ src,
                                                   const float* __restrict__ tgt) {
    const int nc = blockIdx.x;
    const int p  = blockIdx.y;
    const int t  = threadIdx.x;
    const int lane = t & 31;
    const int w    = t >> 5;

    __shared__ __align__(16) __nv_bfloat16 tile[2][ND][72];

    // ---- loader mapping: thread t loads 8 rows (rb + 16s), one float4 each ----
    const int f4 = t & 15;          // float4 column 0..15 (covers 64 floats)
    const int rb = t >> 4;          // base row 0..15
    const float* rowp[8];
#pragma unroll
    for (int s = 0; s < 8; s++) {
        int r = rb + 16 * s;
        const float* base = (r < KD) ? (src + (size_t)(p * KD + r) * DD)
                                     : (tgt + (size_t)(p * KD + (r - KD)) * DD);
        rowp[s] = base + nc * KC + f4 * 4;
    }
    char* tbase[2] = { (char*)&tile[0][0][0], (char*)&tile[1][0][0] };
    uint32_t sts[8];
#pragma unroll
    for (int s = 0; s < 8; s++)
        sts[s] = (uint32_t)((rb + 16 * s) * 144 + f4 * 8);

    // ---- mma mapping: warp tile at (wm, wn) ----
    const int wm = (w & 3) << 5;    // 0,32,64,96
    const int wn = (w >> 2) << 6;   // 0,64
    uint32_t tb[2] = { smem_u32(tbase[0]), smem_u32(tbase[1]) };
    uint32_t aaddr[2][2], baddr[2][4];
#pragma unroll
    for (int b = 0; b < 2; b++) {
#pragma unroll
        for (int mi = 0; mi < 2; mi++)
            aaddr[b][mi] = tb[b] + (uint32_t)((wm + mi * 16 + (lane & 15)) * 144
                                              + (lane >> 4) * 16);
#pragma unroll
        for (int nj = 0; nj < 4; nj++)
            baddr[b][nj] = tb[b] + (uint32_t)((wn + nj * 16 + ((lane >> 4) << 3)
                                               + (lane & 7)) * 144
                                              + ((lane >> 3) & 1) * 16);
    }

    float acc[2][8][4];
#pragma unroll
    for (int mi = 0; mi < 2; mi++)
#pragma unroll
        for (int nj = 0; nj < 8; nj++)
#pragma unroll
            for (int r = 0; r < 4; r++) acc[mi][nj][r] = 0.f;

    float4 v[8];
    // prologue: load chunk 0, stage it
#pragma unroll
    for (int s = 0; s < 8; s++) v[s] = *(const float4*)(rowp[s]);
#pragma unroll
    for (int s = 0; s < 8; s++) {
        __nv_bfloat162 lo = __floats2bfloat162_rn(v[s].x, v[s].y);
        __nv_bfloat162 hi = __floats2bfloat162_rn(v[s].z, v[s].w);
        uint2 u = { *(uint32_t*)&lo, *(uint32_t*)&hi };
        *(uint2*)(tbase[0] + sts[s]) = u;
    }
    __syncthreads();

    uint32_t afr[2][2][4], bfr[2][8][2];   // double-buffered fragments

    for (int ch = 0; ch < NCHK; ch++) {
        const int b = ch & 1;
        // LDG next chunk (in flight during the whole MMA phase)
        if (ch + 1 < NCHK) {
#pragma unroll
            for (int s = 0; s < 8; s++)
                v[s] = *(const float4*)(rowp[s] + (ch + 1) * 64);
        }

        // fragment prologue: k16 = 0 into slot 0
        ldsm_x4(afr[0][0][0], afr[0][0][1], afr[0][0][2], afr[0][0][3], aaddr[b][0]);
        ldsm_x4(afr[0][1][0], afr[0][1][1], afr[0][1][2], afr[0][1][3], aaddr[b][1]);
#pragma unroll
        for (int nj = 0; nj < 4; nj++)
            ldsm_x4(bfr[0][2 * nj][0], bfr[0][2 * nj][1],
                    bfr[0][2 * nj + 1][0], bfr[0][2 * nj + 1][1], baddr[b][nj]);

#pragma unroll
        for (int k16 = 0; k16 < 4; k16++) {
            const int cur = k16 & 1;
            const int nxt = cur ^ 1;
            if (k16 < 3) {   // prefetch fragments for k16+1 while MMAs run
                ldsm_x4(afr[nxt][0][0], afr[nxt][0][1], afr[nxt][0][2],
                        afr[nxt][0][3], aaddr[b][0] + (k16 + 1) * 32);
                ldsm_x4(afr[nxt][1][0], afr[nxt][1][1], afr[nxt][1][2],
                        afr[nxt][1][3], aaddr[b][1] + (k16 + 1) * 32);
#pragma unroll
                for (int nj = 0; nj < 4; nj++)
                    ldsm_x4(bfr[nxt][2 * nj][0], bfr[nxt][2 * nj][1],
                            bfr[nxt][2 * nj + 1][0], bfr[nxt][2 * nj + 1][1],
                            baddr[b][nj] + (k16 + 1) * 32);
            }
#pragma unroll
            for (int mi = 0; mi < 2; mi++)
#pragma unroll
                for (int nj = 0; nj < 8; nj++)
                    mma_bf16(acc[mi][nj], afr[cur][mi], bfr[cur][nj]);
        }

        // STS next chunk after MMA (round-3 ordering), then single barrier
        if (ch + 1 < NCHK) {
            char* dst = tbase[(ch + 1) & 1];
#pragma unroll
            for (int s = 0; s < 8; s++) {
                __nv_bfloat162 lo = __floats2bfloat162_rn(v[s].x, v[s].y);
                __nv_bfloat162 hi = __floats2bfloat162_rn(v[s].z, v[s].w);
                uint2 u = { *(uint32_t*)&lo, *(uint32_t*)&hi };
                *(uint2*)(dst + sts[s]) = u;
            }
            __syncthreads();
        }
    }

    // write accumulators: lane l owns rows (l>>2, l>>2+8), cols (l&3)*2 (+1)
    float* outp = &g_part[nc][p][0][0];
    const int rr = lane >> 2;
    const int cc = (lane & 3) * 2;
#pragma unroll
    for (int mi = 0; mi < 2; mi++)
#pragma unroll
        for (int nj = 0; nj < 8; nj++) {
            int row = wm + mi * 16 + rr;
            int col = wn + nj * 8 + cc;
            *(float2*)&outp[row * ND + col] =
                make_float2(acc[mi][nj][0], acc[mi][nj][1]);
            *(float2*)&outp[(row + 8) * ND + col] =
                make_float2(acc[mi][nj][2], acc[mi][nj][3]);
        }
}

// ---------------------------------------------------------------------------
// Kernel 2: per-split MMD epilogue + fused last-CTA finalize.
// One CTA per split, 256 threads. Quadrant q = t>>6, u = t&63:
// row i = (q>>1)*64 + u, cols jb = (q&1)*64 .. +63. l2 held in registers.
// Exp trick: sum_m exp(-l2*inv[m]) = z + z^2 + z^4 + z^8 + z^16.
// ---------------------------------------------------------------------------
__global__ void __launch_bounds__(256) mmd_kernel(float* __restrict__ out) {
    const int p = blockIdx.x;
    const int t = threadIdx.x;
    const int q = t >> 6;
    const int u = t & 63;
    const int i = ((q >> 1) << 6) + u;
    const int jb = (q & 1) << 6;

    __shared__ float diag[ND];
    __shared__ float red[256], red2[256];
    __shared__ float s_bw;

    const float* p0 = &g_part[0][p][0][0];
    const float* p1 = &g_part[1][p][0][0];

    float g[64];
#pragma unroll
    for (int j4 = 0; j4 < 16; j4++) {
        float4 A = *(const float4*)&p0[i * ND + jb + j4 * 4];
        float4 B = *(const float4*)&p1[i * ND + jb + j4 * 4];
        g[4 * j4 + 0] = A.x + B.x;
        g[4 * j4 + 1] = A.y + B.y;
        g[4 * j4 + 2] = A.z + B.z;
        g[4 * j4 + 3] = A.w + B.w;
    }
    if (t < ND) diag[t] = p0[t * ND + t] + p1[t * ND + t];
    __syncthreads();

    const float di = diag[i];

    // Pass 1: l2 into g, sum(l2), max(l2)
    float lsum = 0.f, lmax = 0.f;
#pragma unroll
    for (int jj = 0; jj < 64; jj++) {
        float l2 = di + diag[jb + jj] - 2.f * g[jj];
        g[jj] = l2;
        lsum += l2;
        lmax = fmaxf(lmax, l2);
    }
    red[t] = lsum;
    red2[t] = lmax;
    __syncthreads();
#pragma unroll
    for (int s = 128; s > 0; s >>= 1) {
        if (t < s) {
            red[t] += red[t + s];
            red2[t] = fmaxf(red2[t], red2[t + s]);
        }
        __syncthreads();
    }
    if (t == 0) {
        s_bw = red[0] / (float)(ND * ND - ND) * 0.25f;  // /(n^2-n)/2^(5/2 floor)
        g_l2max[p] = red2[0];
    }
    __syncthreads();

    const float inv4 = 1.f / (s_bw * 16.f + 1e-9f);

    // Pass 2: 5-RBF sum via repeated squaring (1 expf per element)
    float qs = 0.f;
#pragma unroll
    for (int jj = 0; jj < 64; jj++) {
        float z = __expf(-g[jj] * inv4);
        float z2 = z * z;
        float z4 = z2 * z2;
        float z8 = z4 * z4;
        float z16 = z8 * z8;
        qs += z + z2 + z4 + z8 + z16;
    }
    red[t] = qs;
    __syncthreads();
#pragma unroll
    for (int s = 32; s > 0; s >>= 1) {
        if (u < s) red[t] += red[t + s];
        __syncthreads();
    }
    if (u == 0) g_sums[p][q] = red[t];   // q: 0=xx, 1=xy, 2=yx, 3=yy

    // ---- fused finalize: last CTA to finish does the fixed-order reduction ----
    __syncthreads();
    if (t == 0) {
        __threadfence();
        unsigned int done = atomicAdd(&g_ctr, 1u);
        if (done == PD - 1) {
            __threadfence();
            float X = 0.f, Y = 0.f, XY = 0.f, YX = 0.f;
            for (int k = 0; k < PD; k++) {
                X  += g_sums[k][0] * (1.f / 4096.f);
                XY += g_sums[k][1] * (1.f / 4096.f);
                YX += g_sums[k][2] * (1.f / 4096.f);
                Y  += g_sums[k][3] * (1.f / 4096.f);
            }
            out[0] = (X + Y - XY - YX) * (1.f / 64.f);  // total_loss
            out[1] = g_l2max[PD - 1];                   // max(l2[-1])
            out[2] = X * (1.f / 64.f);
            out[3] = Y * (1.f / 64.f);
            out[4] = XY * (1.f / 64.f);
            out[5] = YX * (1.f / 64.f);
            g_ctr = 0;   // reset for the next (graph-replayed) launch
        }
    }
}

extern "C" void kernel_launch(void* const* d_in, const int* in_sizes, int n_in,
                              void* d_out, int out_size) {
    const float* src = (const float*)d_in[0];
    const float* tgt = (const float*)d_in[1];

    dim3 g1(NCH, PD);
    gram_kernel<<<g1, 256>>>(src, tgt);
    mmd_kernel<<<PD, 256>>>((float*)d_out);
}

// round 6
// speedup vs baseline: 1.6150x; 1.0408x over previous
#include <cuda_runtime.h>
#include <cuda_bf16.h>
#include <stdint.h>

// Problem constants
#define PD 64      // splits
#define KD 64      // samples per side
#define ND 128     // points per split
#define DD 2048    // feature dim
#define NCH 2      // D halves -> 128 CTAs for the gram stage
#define KC (DD / NCH)     // 1024 K per CTA
#define NCHK (KC / 64)    // 16 chunks of 64 K

// Scratch (device globals; no allocation allowed)
__device__ float g_part[NCH][PD][ND][ND];  // partial grams, 8 MB (L2-resident)
__device__ float g_bw[NCH][PD][2];         // per-half (sum(G), trace(G))
__device__ float g_sums[PD][4];            // xx, xy, yx, yy per split
__device__ float g_l2max4[4];              // quadrant maxes for split PD-1
__device__ unsigned int g_ctr;             // zero-init; self-resetting

__device__ __forceinline__ uint32_t smem_u32(const void* p) {
    uint32_t a;
    asm("{ .reg .u64 t; cvta.to.shared.u64 t, %1; cvt.u32.u64 %0, t; }"
        : "=r"(a) : "l"(p));
    return a;
}

__device__ __forceinline__ void ldsm_x4(uint32_t& r0, uint32_t& r1, uint32_t& r2,
                                        uint32_t& r3, uint32_t addr) {
    asm volatile("ldmatrix.sync.aligned.m8n8.x4.shared.b16 {%0,%1,%2,%3}, [%4];"
                 : "=r"(r0), "=r"(r1), "=r"(r2), "=r"(r3) : "r"(addr));
}

__device__ __forceinline__ void mma_bf16(float* c, const uint32_t* a, const uint32_t* b) {
    asm volatile(
        "mma.sync.aligned.m16n8k16.row.col.f32.bf16.bf16.f32 "
        "{%0,%1,%2,%3}, {%4,%5,%6,%7}, {%8,%9}, {%0,%1,%2,%3};"
        : "+f"(c[0]), "+f"(c[1]), "+f"(c[2]), "+f"(c[3])
        : "r"(a[0]), "r"(a[1]), "r"(a[2]), "r"(a[3]), "r"(b[0]), "r"(b[1]));
}

// ---------------------------------------------------------------------------
// Kernel 1: partial Gram via HMMA (R5 main loop, proven). New epilogue also
// emits (sum, trace) of the partial gram so the bandwidth needs no extra pass.
// ---------------------------------------------------------------------------
__global__ void __launch_bounds__(256) gram_kernel(const float* __restrict__ src,
                                                   const float* __restrict__ tgt) {
    const int nc = blockIdx.x;
    const int p  = blockIdx.y;
    const int t  = threadIdx.x;
    const int lane = t & 31;
    const int w    = t >> 5;

    __shared__ __align__(16) __nv_bfloat16 tile[2][ND][72];
    __shared__ float red1[8], red2[8];

    // ---- loader mapping: thread t loads 8 rows (rb + 16s), one float4 each ----
    const int f4 = t & 15;
    const int rb = t >> 4;
    const float* rowp[8];
#pragma unroll
    for (int s = 0; s < 8; s++) {
        int r = rb + 16 * s;
        const float* base = (r < KD) ? (src + (size_t)(p * KD + r) * DD)
                                     : (tgt + (size_t)(p * KD + (r - KD)) * DD);
        rowp[s] = base + nc * KC + f4 * 4;
    }
    char* tbase[2] = { (char*)&tile[0][0][0], (char*)&tile[1][0][0] };
    uint32_t sts[8];
#pragma unroll
    for (int s = 0; s < 8; s++)
        sts[s] = (uint32_t)((rb + 16 * s) * 144 + f4 * 8);

    // ---- mma mapping: warp tile at (wm, wn) ----
    const int wm = (w & 3) << 5;
    const int wn = (w >> 2) << 6;
    uint32_t tb[2] = { smem_u32(tbase[0]), smem_u32(tbase[1]) };
    uint32_t aaddr[2][2], baddr[2][4];
#pragma unroll
    for (int b = 0; b < 2; b++) {
#pragma unroll
        for (int mi = 0; mi < 2; mi++)
            aaddr[b][mi] = tb[b] + (uint32_t)((wm + mi * 16 + (lane & 15)) * 144
                                              + (lane >> 4) * 16);
#pragma unroll
        for (int nj = 0; nj < 4; nj++)
            baddr[b][nj] = tb[b] + (uint32_t)((wn + nj * 16 + ((lane >> 4) << 3)
                                               + (lane & 7)) * 144
                                              + ((lane >> 3) & 1) * 16);
    }

    float acc[2][8][4];
#pragma unroll
    for (int mi = 0; mi < 2; mi++)
#pragma unroll
        for (int nj = 0; nj < 8; nj++)
#pragma unroll
            for (int r = 0; r < 4; r++) acc[mi][nj][r] = 0.f;

    float4 v[8];
#pragma unroll
    for (int s = 0; s < 8; s++) v[s] = *(const float4*)(rowp[s]);
#pragma unroll
    for (int s = 0; s < 8; s++) {
        __nv_bfloat162 lo = __floats2bfloat162_rn(v[s].x, v[s].y);
        __nv_bfloat162 hi = __floats2bfloat162_rn(v[s].z, v[s].w);
        uint2 u = { *(uint32_t*)&lo, *(uint32_t*)&hi };
        *(uint2*)(tbase[0] + sts[s]) = u;
    }
    __syncthreads();

    uint32_t afr[2][2][4], bfr[2][8][2];

    for (int ch = 0; ch < NCHK; ch++) {
        const int b = ch & 1;
        if (ch + 1 < NCHK) {
#pragma unroll
            for (int s = 0; s < 8; s++)
                v[s] = *(const float4*)(rowp[s] + (ch + 1) * 64);
        }

        ldsm_x4(afr[0][0][0], afr[0][0][1], afr[0][0][2], afr[0][0][3], aaddr[b][0]);
        ldsm_x4(afr[0][1][0], afr[0][1][1], afr[0][1][2], afr[0][1][3], aaddr[b][1]);
#pragma unroll
        for (int nj = 0; nj < 4; nj++)
            ldsm_x4(bfr[0][2 * nj][0], bfr[0][2 * nj][1],
                    bfr[0][2 * nj + 1][0], bfr[0][2 * nj + 1][1], baddr[b][nj]);

#pragma unroll
        for (int k16 = 0; k16 < 4; k16++) {
            const int cur = k16 & 1;
            const int nxt = cur ^ 1;
            if (k16 < 3) {
                ldsm_x4(afr[nxt][0][0], afr[nxt][0][1], afr[nxt][0][2],
                        afr[nxt][0][3], aaddr[b][0] + (k16 + 1) * 32);
                ldsm_x4(afr[nxt][1][0], afr[nxt][1][1], afr[nxt][1][2],
                        afr[nxt][1][3], aaddr[b][1] + (k16 + 1) * 32);
#pragma unroll
                for (int nj = 0; nj < 4; nj++)
                    ldsm_x4(bfr[nxt][2 * nj][0], bfr[nxt][2 * nj][1],
                            bfr[nxt][2 * nj + 1][0], bfr[nxt][2 * nj + 1][1],
                            baddr[b][nj] + (k16 + 1) * 32);
            }
#pragma unroll
            for (int mi = 0; mi < 2; mi++)
#pragma unroll
                for (int nj = 0; nj < 8; nj++)
                    mma_bf16(acc[mi][nj], afr[cur][mi], bfr[cur][nj]);
        }

        if (ch + 1 < NCHK) {
            char* dst = tbase[(ch + 1) & 1];
#pragma unroll
            for (int s = 0; s < 8; s++) {
                __nv_bfloat162 lo = __floats2bfloat162_rn(v[s].x, v[s].y);
                __nv_bfloat162 hi = __floats2bfloat162_rn(v[s].z, v[s].w);
                uint2 u = { *(uint32_t*)&lo, *(uint32_t*)&hi };
                *(uint2*)(dst + sts[s]) = u;
            }
            __syncthreads();
        }
    }

    // ---- writeout + (sum, trace) epilogue ----
    float* outp = &g_part[nc][p][0][0];
    const int rr = lane >> 2;
    const int cc = (lane & 3) * 2;
    float s1 = 0.f, s2 = 0.f;
#pragma unroll
    for (int mi = 0; mi < 2; mi++)
#pragma unroll
        for (int nj = 0; nj < 8; nj++) {
            int row = wm + mi * 16 + rr;
            int col = wn + nj * 8 + cc;
            *(float2*)&outp[row * ND + col] =
                make_float2(acc[mi][nj][0], acc[mi][nj][1]);
            *(float2*)&outp[(row + 8) * ND + col] =
                make_float2(acc[mi][nj][2], acc[mi][nj][3]);
            s1 += (acc[mi][nj][0] + acc[mi][nj][1]) +
                  (acc[mi][nj][2] + acc[mi][nj][3]);
            if (row == col)         s2 += acc[mi][nj][0];
            if (row == col + 1)     s2 += acc[mi][nj][1];
            if (row + 8 == col)     s2 += acc[mi][nj][2];
            if (row + 8 == col + 1) s2 += acc[mi][nj][3];
        }
    // warp shuffle reduce (deterministic xor tree)
#pragma unroll
    for (int m = 16; m > 0; m >>= 1) {
        s1 += __shfl_xor_sync(0xFFFFFFFFu, s1, m);
        s2 += __shfl_xor_sync(0xFFFFFFFFu, s2, m);
    }
    if (lane == 0) { red1[w] = s1; red2[w] = s2; }
    __syncthreads();
    if (t == 0) {
        float a = 0.f, b2 = 0.f;
#pragma unroll
        for (int k = 0; k < 8; k++) { a += red1[k]; b2 += red2[k]; }
        g_bw[nc][p][0] = a;    // sum of partial gram
        g_bw[nc][p][1] = b2;   // trace of partial gram
    }
}

// ---------------------------------------------------------------------------
// Kernel 2: 256 CTAs — one 64x64 quadrant per CTA (4 per split).
// bw derived analytically: sum(l2) = 2*n*trace(G) - 2*sum(G).
// Single exp pass; shuffle reductions; last-CTA fused finalize.
// ---------------------------------------------------------------------------
__global__ void __launch_bounds__(256) mmd_kernel(float* __restrict__ out) {
    const int b = blockIdx.x;
    const int p = b >> 2;
    const int q = b & 3;               // bit1 = i-half, bit0 = j-half
    const int t = threadIdx.x;
    const int lane = t & 31;
    const int w = t >> 5;

    const int i  = ((q >> 1) << 6) + (t >> 2);      // row (64 rows/CTA)
    const int jb = ((q & 1) << 6) + (t & 3) * 16;   // 16-col strip

    __shared__ float diag[ND];
    __shared__ float sred[8], sred2[8];

    const float* p0 = &g_part[0][p][0][0];
    const float* p1 = &g_part[1][p][0][0];

    if (t < ND) diag[t] = p0[t * (ND + 1)] + p1[t * (ND + 1)];

    // bandwidth from gram aggregates
    const float gs = g_bw[0][p][0] + g_bw[1][p][0];
    const float tr = g_bw[0][p][1] + g_bw[1][p][1];
    const float sumL2 = 2.f * (float)ND * tr - 2.f * gs;
    const float bw = sumL2 / (float)(ND * ND - ND) * 0.25f;
    const float inv4 = 1.f / (bw * 16.f + 1e-9f);

    // load 16 gram entries (both halves), combine
    float g[16];
#pragma unroll
    for (int j4 = 0; j4 < 4; j4++) {
        float4 A = *(const float4*)&p0[i * ND + jb + j4 * 4];
        float4 B = *(const float4*)&p1[i * ND + jb + j4 * 4];
        g[4 * j4 + 0] = A.x + B.x;
        g[4 * j4 + 1] = A.y + B.y;
        g[4 * j4 + 2] = A.z + B.z;
        g[4 * j4 + 3] = A.w + B.w;
    }
    __syncthreads();

    const float di = diag[i];
    float qs = 0.f, lmax = 0.f;
#pragma unroll
    for (int jj = 0; jj < 16; jj++) {
        float l2 = di + diag[jb + jj] - 2.f * g[jj];
        lmax = fmaxf(lmax, l2);
        float z = __expf(-l2 * inv4);
        float z2 = z * z;
        float z4 = z2 * z2;
        float z8 = z4 * z4;
        float z16 = z8 * z8;
        qs += z + z2 + z4 + z8 + z16;
    }

#pragma unroll
    for (int m = 16; m > 0; m >>= 1) {
        qs += __shfl_xor_sync(0xFFFFFFFFu, qs, m);
        lmax = fmaxf(lmax, __shfl_xor_sync(0xFFFFFFFFu, lmax, m));
    }
    if (lane == 0) { sred[w] = qs; sred2[w] = lmax; }
    __syncthreads();

    if (t == 0) {
        float s = 0.f, m = 0.f;
#pragma unroll
        for (int k = 0; k < 8; k++) { s += sred[k]; m = fmaxf(m, sred2[k]); }
        g_sums[p][q] = s;                        // q: 0=xx, 1=xy, 2=yx, 3=yy
        if (p == PD - 1) g_l2max4[q] = m;

        __threadfence();
        unsigned int done = atomicAdd(&g_ctr, 1u);
        if (done == 4 * PD - 1) {
            __threadfence();
            float X = 0.f, Y = 0.f, XY = 0.f, YX = 0.f;
            for (int k = 0; k < PD; k++) {
                X  += g_sums[k][0] * (1.f / 4096.f);
                XY += g_sums[k][1] * (1.f / 4096.f);
                YX += g_sums[k][2] * (1.f / 4096.f);
                Y  += g_sums[k][3] * (1.f / 4096.f);
            }
            float mx = fmaxf(fmaxf(g_l2max4[0], g_l2max4[1]),
                             fmaxf(g_l2max4[2], g_l2max4[3]));
            out[0] = (X + Y - XY - YX) * (1.f / 64.f);  // total_loss
            out[1] = mx;                                // max(l2[-1])
            out[2] = X * (1.f / 64.f);
            out[3] = Y * (1.f / 64.f);
            out[4] = XY * (1.f / 64.f);
            out[5] = YX * (1.f / 64.f);
            g_ctr = 0;   // reset for graph replay
        }
    }
}

extern "C" void kernel_launch(void* const* d_in, const int* in_sizes, int n_in,
                              void* d_out, int out_size) {
    const float* src = (const float*)d_in[0];
    const float* tgt = (const float*)d_in[1];

    dim3 g1(NCH, PD);
    gram_kernel<<<g1, 256>>>(src, tgt);
    mmd_kernel<<<4 * PD, 256>>>((float*)d_out);
}